// round 12
// baseline (speedup 1.0000x reference)
#include <cuda_runtime.h>
#include <cuda_fp16.h>
#include <cstdint>

#define N_NODES 200000
#define DEG 16
#define T_ROUNDS 3
#define HDIM 70
#define HSTRIDE 72
#define NKT 10              // K padded to 160 = 10 * 16
#define NB 72
#define WARPS 9
#define THREADS 288
#define BMT 29              // m-tiles (16 nodes) per block
#define BM (BMT * 16)       // 464 nodes per block
#define NBLK 432            // 432 * 464 = 200448 >= 200000; one wave (<=444 resident)
#define SH 84               // A smem row stride in words (336B; ldmatrix conflict-free)
#define IMGW (16 * SH)      // 1344 words per image

#define RBLOCKS 1024
#define RTHREADS 128

// ---------------- device scratch (static: no allocation) ----------------
__device__ float    g_h[2][N_NODES * HSTRIDE];
__device__ float    g_me6T[DEG][N_NODES * 6];    // slice-major: contiguous per j
__device__ int      g_nbrT[DEG][N_NODES];        // slice-major: contiguous per j
__device__ float    g_Wtmp[160 * NB];
__device__ uint32_t g_Bfhi[WARPS * NKT * 2 * 32];   // B fragments (fp16x2), mma order
__device__ uint32_t g_Bflo[WARPS * NKT * 2 * 32];
__device__ float    g_btot[NB];
__device__ float    g_Rc[HDIM * 128];
__device__ float    g_partial[RBLOCKS * 128];

// ---------------- helpers ----------------
__device__ __forceinline__ uint32_t pack_h2(__half a, __half b) {
    __half2 t = __halves2half2(a, b);
    return *(uint32_t*)&t;
}
__device__ __forceinline__ uint32_t h2u(__half2 h) { return *(uint32_t*)&h; }

#define MMA16(C,a0,a1,a2,a3,b0,b1)                                           \
    asm volatile("mma.sync.aligned.m16n8k16.row.col.f32.f16.f16.f32 "        \
        "{%0,%1,%2,%3}, {%4,%5,%6,%7}, {%8,%9}, {%0,%1,%2,%3};"              \
        : "+f"(C[0]), "+f"(C[1]), "+f"(C[2]), "+f"(C[3])                     \
        : "r"(a0), "r"(a1), "r"(a2), "r"(a3), "r"(b0), "r"(b1))

#define LDSM4(R, addr)                                                       \
    asm volatile("ldmatrix.sync.aligned.m8n8.x4.shared.b16 {%0,%1,%2,%3}, [%4];" \
        : "=r"((R)[0]), "=r"((R)[1]), "=r"((R)[2]), "=r"((R)[3]) : "r"(addr))

// ---------------- weight folding -> fp16 mma-fragment images ----------------
// K-slot map: k in [0,70)=U1 ; [72,142)=(Vw@U2) ; [144,150)=U3 ; else 0.
__global__ void prep_kernel(const float* __restrict__ Vw, const float* __restrict__ Vb,
                            const float* __restrict__ Uw, const float* __restrict__ Ub,
                            const float* __restrict__ Rw) {
    int tid = threadIdx.x;
    for (int i = tid; i < 160 * NB; i += blockDim.x) {
        int k = i / NB, n = i % NB;
        float w = 0.f;
        if (n < HDIM) {
            if (k < 70) {
                w = Uw[k * HDIM + n];
            } else if (k >= 72 && k < 142) {
                int p = k - 72;
                float s = 0.f;
                for (int q = 0; q < 70; ++q) s += Vw[p * 70 + q] * Uw[(70 + q) * HDIM + n];
                w = s;
            } else if (k >= 144 && k < 150) {
                w = Uw[(140 + (k - 144)) * HDIM + n];
            }
        }
        g_Wtmp[i] = w;
    }
    __syncthreads();
    // B fragment (m16n8k16): idx = ((w*NKT + kt)*2 + r)*32 + lane
    // packs fp16x2 of W[k0][n], W[k0+1][n], k0 = kt*16 + (lane%4)*2 + 8r, n = w*8 + lane/4
    for (int idx = tid; idx < WARPS * NKT * 2 * 32; idx += blockDim.x) {
        int lane = idx & 31;
        int t = idx >> 5;
        int r = t & 1; t >>= 1;
        int kt = t % NKT;
        int w = t / NKT;
        int k0 = kt * 16 + (lane & 3) * 2 + 8 * r;
        int n = w * 8 + (lane >> 2);
        float v0 = g_Wtmp[k0 * NB + n];
        float v1 = g_Wtmp[(k0 + 1) * NB + n];
        __half h0 = __float2half_rn(v0), h1 = __float2half_rn(v1);
        g_Bfhi[idx] = pack_h2(h0, h1);
        g_Bflo[idx] = pack_h2(__float2half_rn(v0 - __half2float(h0)),
                              __float2half_rn(v1 - __half2float(h1)));
    }
    for (int k = tid; k < NB; k += blockDim.x) {
        float v = 0.f;
        if (k < HDIM) {
            v = Ub[k];
            for (int q = 0; q < 70; ++q) v += Vb[q] * Uw[(70 + q) * HDIM + k];
        }
        g_btot[k] = v;
    }
    for (int i = tid; i < HDIM * 128; i += blockDim.x) {
        int p = i / 128, k = i % 128;
        g_Rc[i] = Rw[p * 128 + k] + Rw[(70 + p) * 128 + k];
    }
}

// ---------------- edge messages -> slice-major; nbr transpose ----------------
__global__ void edge_kernel(const float* __restrict__ ef,
                            const float* __restrict__ Ew,
                            const float* __restrict__ Eb,
                            const int* __restrict__ nbr) {
    int i = blockIdx.x * blockDim.x + threadIdx.x;
    if (i >= N_NODES * DEG) return;
    int node = i / DEG, j = i % DEG;
    float e[6];
#pragma unroll
    for (int d = 0; d < 6; ++d) e[d] = ef[i * 6 + d];
#pragma unroll
    for (int c = 0; c < 6; ++c) {
        float s = __ldg(&Eb[c]);
#pragma unroll
        for (int d = 0; d < 6; ++d) s += e[d] * __ldg(&Ew[d * 6 + c]);
        g_me6T[j][node * 6 + c] = s;
    }
    g_nbrT[j][node] = nbr[i];
}

__global__ void init_kernel(const float* __restrict__ h) {
    int i = blockIdx.x * blockDim.x + threadIdx.x;
    if (i >= N_NODES * HSTRIDE) return;
    int v = i / HSTRIDE, k = i % HSTRIDE;
    g_h[0][i] = (k < HDIM) ? h[v * HDIM + k] : 0.f;
}

// ---------------- split fill: LDG phase (regs) + STS phase (smem) ----------------
// Chunk e of m-tile: r = e/40 (row), q = e%40 (float4 within padded-160 cols).
// cols: self [0,72) | gather [72,144) | me [144,150) | pad [150,160)
__device__ __forceinline__ float4 ldg_chunk(const float* __restrict__ hin,
                                            const int* __restrict__ sg,
                                            const float* __restrict__ mej,
                                            int base, int mt, int r, int q) {
    int node = base + mt * 16 + r;
    if (node > N_NODES - 1) node = N_NODES - 1;
    if (q < 18) {
        return *(const float4*)(hin + (size_t)node * HSTRIDE + 4 * q);
    } else if (q < 36) {
        int gi = sg[mt * 16 + r];
        return *(const float4*)(hin + (size_t)gi * HSTRIDE + 4 * (q - 18));
    } else if (q == 36) {
        const float* me = mej + (size_t)node * 6;
        float2 a = *(const float2*)me;
        float2 b = *(const float2*)(me + 2);
        return make_float4(a.x, a.y, b.x, b.y);
    } else if (q == 37) {
        const float* me = mej + (size_t)node * 6;
        float2 c = *(const float2*)(me + 4);
        return make_float4(c.x, c.y, 0.f, 0.f);
    }
    return make_float4(0.f, 0.f, 0.f, 0.f);   // pad
}

// A smem layout: row-linear fp16 (16 halves per ktile block), hi at [0, IMGW), lo at +IMGW.
__device__ __forceinline__ void sts_chunk(uint32_t* __restrict__ a, int r, int q, float4 v) {
    int base = r * SH + 2 * q;
    __half2 h01 = __float22half2_rn(make_float2(v.x, v.y));
    __half2 h23 = __float22half2_rn(make_float2(v.z, v.w));
    float2 f01 = __half22float2(h01);
    float2 f23 = __half22float2(h23);
    __half2 l01 = __float22half2_rn(make_float2(v.x - f01.x, v.y - f01.y));
    __half2 l23 = __float22half2_rn(make_float2(v.z - f23.x, v.w - f23.y));
    *(uint2*)(a + base)        = make_uint2(h2u(h01), h2u(h23));
    *(uint2*)(a + IMGW + base) = make_uint2(h2u(l01), h2u(l23));
}

// ---------------- one MP step on tensor cores (fp16 3-term split) ----------------
__global__ __launch_bounds__(THREADS, 3)
void step_kernel(int j, int src) {
    __shared__ uint32_t sA[2][2 * IMGW];      // [buffer][hi | lo]
    __shared__ int s_gidx[BM];

    const float* __restrict__ hin = g_h[src];
    float* __restrict__ hout = g_h[src ^ 1];
    const int* __restrict__ nbrj = g_nbrT[j];
    const float* __restrict__ mej = g_me6T[j];
    int tid = threadIdx.x, w = tid >> 5, lane = tid & 31;
    int base = blockIdx.x * BM;

    // B fragments for this warp's 8-column strip: 40 registers (once per block)
    uint32_t Bhi[NKT][2], Blo[NKT][2];
#pragma unroll
    for (int kt = 0; kt < NKT; ++kt)
#pragma unroll
        for (int r = 0; r < 2; ++r) {
            int idx = ((w * NKT + kt) * 2 + r) * 32 + lane;
            Bhi[kt][r] = g_Bfhi[idx];
            Blo[kt][r] = g_Bflo[idx];
        }
    int col = w * 8 + (lane & 3) * 2;
    float bb0 = g_btot[col], bb1 = g_btot[col + 1];

    // gather indices for all 464 nodes of this block
    for (int i = tid; i < BM; i += THREADS) {
        int node = base + i;
        if (node > N_NODES - 1) node = N_NODES - 1;
        s_gidx[i] = __ldg(&nbrj[node]);
    }
    __syncthreads();

    // per-thread chunk ownership: 640 chunks per m-tile; e0 = tid, e1 = tid+288, e2 for tid<64
    const int e0 = tid, e1 = tid + THREADS;
    const int r0 = e0 / 40, q0 = e0 - r0 * 40;
    const int r1 = e1 / 40, q1 = e1 - r1 * 40;
    const bool has2 = (tid < 16 * 40 - 2 * THREADS);   // 64 threads
    const int e2 = tid + 2 * THREADS;
    const int r2 = e2 / 40, q2 = e2 - r2 * 40;

    // prologue: fill tile 0
    {
        float4 v0 = ldg_chunk(hin, s_gidx, mej, base, 0, r0, q0);
        float4 v1 = ldg_chunk(hin, s_gidx, mej, base, 0, r1, q1);
        float4 v2 = has2 ? ldg_chunk(hin, s_gidx, mej, base, 0, r2, q2)
                         : make_float4(0.f, 0.f, 0.f, 0.f);
        sts_chunk(sA[0], r0, q0, v0);
        sts_chunk(sA[0], r1, q1, v1);
        if (has2) sts_chunk(sA[0], r2, q2, v2);
    }
    __syncthreads();

    // ldmatrix lane address
    const int lrow = (lane & 7) + 8 * ((lane >> 3) & 1);
    const int loff = (lrow * SH + ((lane >> 4) & 1) * 4) * 4;   // bytes
    const uint32_t sb0 = (uint32_t)__cvta_generic_to_shared(sA[0]);
    const uint32_t sb1 = (uint32_t)__cvta_generic_to_shared(sA[1]);

#pragma unroll 1
    for (int mt = 0; mt < BMT; ++mt) {
        // (1) issue next tile's global loads into registers
        float4 v0, v1, v2;
        if (mt < BMT - 1) {
            v0 = ldg_chunk(hin, s_gidx, mej, base, mt + 1, r0, q0);
            v1 = ldg_chunk(hin, s_gidx, mej, base, mt + 1, r1, q1);
            if (has2) v2 = ldg_chunk(hin, s_gidx, mej, base, mt + 1, r2, q2);
        }

        // (2) compute current tile
        const uint32_t ahi = ((mt & 1) ? sb1 : sb0) + loff;
        const uint32_t alo = ahi + IMGW * 4;
        float ch[4] = {0.f, 0.f, 0.f, 0.f};
        float cc[4] = {0.f, 0.f, 0.f, 0.f};

#pragma unroll
        for (int kt = 0; kt < NKT; ++kt) {
            uint32_t A[4], L[4];
            LDSM4(A, ahi + kt * 32);
            LDSM4(L, alo + kt * 32);
            MMA16(ch, A[0], A[1], A[2], A[3], Bhi[kt][0], Bhi[kt][1]);
            MMA16(cc, A[0], A[1], A[2], A[3], Blo[kt][0], Blo[kt][1]);
            MMA16(cc, L[0], L[1], L[2], L[3], Bhi[kt][0], Bhi[kt][1]);
        }

        // (3) convert + store next tile into the other buffer
        if (mt < BMT - 1) {
            uint32_t* na = sA[(mt + 1) & 1];
            sts_chunk(na, r0, q0, v0);
            sts_chunk(na, r1, q1, v1);
            if (has2) sts_chunk(na, r2, q2, v2);
        }

        // (4) epilogue: bias + relu, store two float2 per thread
        int row = lane >> 2;
        int node0 = base + mt * 16 + row;
        if (node0 < N_NODES) {
            float2 o;
            o.x = fmaxf((ch[0] + cc[0]) + bb0, 0.f);
            o.y = fmaxf((ch[1] + cc[1]) + bb1, 0.f);
            *(float2*)(hout + (size_t)node0 * HSTRIDE + col) = o;
        }
        int node1 = node0 + 8;
        if (node1 < N_NODES) {
            float2 o;
            o.x = fmaxf((ch[2] + cc[2]) + bb0, 0.f);
            o.y = fmaxf((ch[3] + cc[3]) + bb1, 0.f);
            *(float2*)(hout + (size_t)node1 * HSTRIDE + col) = o;
        }
        __syncthreads();
    }
}

// ---------------- readout ----------------
__global__ __launch_bounds__(RTHREADS)
void readout_kernel(const float* __restrict__ Rb) {
    int k = threadIdx.x;
    float rc[HSTRIDE];
#pragma unroll
    for (int p = 0; p < HDIM; ++p) rc[p] = g_Rc[p * 128 + k];
    rc[70] = 0.f; rc[71] = 0.f;
    float rb = Rb[k];

    int per = (N_NODES + RBLOCKS - 1) / RBLOCKS;
    int n0 = blockIdx.x * per;
    int n1 = n0 + per; if (n1 > N_NODES) n1 = N_NODES;

    float acc = 0.f;
    for (int n = n0; n < n1; ++n) {
        const float4* hp = (const float4*)(g_h[0] + (size_t)n * HSTRIDE);
        float s = rb;
#pragma unroll
        for (int q = 0; q < HSTRIDE / 4; ++q) {
            float4 hv = __ldg(&hp[q]);
            s += hv.x * rc[4 * q] + hv.y * rc[4 * q + 1]
               + hv.z * rc[4 * q + 2] + hv.w * rc[4 * q + 3];
        }
        acc += fmaxf(s, 0.f);
    }
    g_partial[blockIdx.x * 128 + k] = acc;
}

__global__ void final_kernel(const float* __restrict__ S1w, const float* __restrict__ S1b,
                             const float* __restrict__ S2w, const float* __restrict__ S2b,
                             const float* __restrict__ Hw,  const float* __restrict__ Hb,
                             const float* __restrict__ Ow,  const float* __restrict__ Ob,
                             float* __restrict__ out) {
    __shared__ float fm[128], av[128], bv[100], cv[100];
    int t = threadIdx.x;
    float s = 0.f;
    for (int b = 0; b < RBLOCKS; ++b) s += g_partial[b * 128 + t];
    fm[t] = s;
    __syncthreads();
    float v = S1b[t];
    for (int p = 0; p < 128; ++p) v += fm[p] * S1w[p * 128 + t];
    av[t] = fmaxf(v, 0.f);
    __syncthreads();
    if (t < 100) {
        v = S2b[t];
        for (int p = 0; p < 128; ++p) v += av[p] * S2w[p * 100 + t];
        bv[t] = v;
    }
    __syncthreads();
    if (t < 100) {
        v = Hb[t];
        for (int p = 0; p < 100; ++p) v += bv[p] * Hw[p * 100 + t];
        cv[t] = fmaxf(v, 0.f);
    }
    __syncthreads();
    if (t == 0) {
        v = Ob[0];
        for (int p = 0; p < 100; ++p) v += cv[p] * Ow[p];
        out[0] = v;
    }
}

extern "C" void kernel_launch(void* const* d_in, const int* in_sizes, int n_in,
                              void* d_out, int out_size) {
    const float* h   = (const float*)d_in[0];
    const float* ef  = (const float*)d_in[1];
    const int*   nbr = (const int*)d_in[2];
    const float* Vw  = (const float*)d_in[3];
    const float* Vb  = (const float*)d_in[4];
    const float* Ew  = (const float*)d_in[5];
    const float* Eb  = (const float*)d_in[6];
    const float* Uw  = (const float*)d_in[7];
    const float* Ub  = (const float*)d_in[8];
    const float* Rw  = (const float*)d_in[9];
    const float* Rb  = (const float*)d_in[10];
    const float* S1w = (const float*)d_in[11];
    const float* S1b = (const float*)d_in[12];
    const float* S2w = (const float*)d_in[13];
    const float* S2b = (const float*)d_in[14];
    const float* Hw  = (const float*)d_in[15];
    const float* Hb  = (const float*)d_in[16];
    const float* Ow  = (const float*)d_in[17];
    const float* Ob  = (const float*)d_in[18];
    float* out = (float*)d_out;

    prep_kernel<<<1, 256>>>(Vw, Vb, Uw, Ub, Rw);
    edge_kernel<<<(N_NODES * DEG + 255) / 256, 256>>>(ef, Ew, Eb, nbr);
    init_kernel<<<(N_NODES * HSTRIDE + 255) / 256, 256>>>(h);

    int src = 0;
    for (int r = 0; r < T_ROUNDS; ++r) {
        for (int j = 0; j < DEG; ++j) {
            step_kernel<<<NBLK, THREADS>>>(j, src);
            src ^= 1;
        }
    }
    // 48 steps (even) -> final state in g_h[0]
    readout_kernel<<<RBLOCKS, RTHREADS>>>(Rb);
    final_kernel<<<1, 128>>>(S1w, S1b, S2w, S2b, Hw, Hb, Ow, Ob, out);
}

// round 13
// speedup vs baseline: 1.0012x; 1.0012x over previous
#include <cuda_runtime.h>
#include <cuda_fp16.h>
#include <cstdint>

#define N_NODES 200000
#define DEG 16
#define T_ROUNDS 3
#define HDIM 70
#define HSTRIDE 72
#define NKT 10              // K padded to 160 = 10 * 16
#define NB 72
#define WARPS 9
#define THREADS 288
#define BMT 29              // m-tiles (16 nodes) per block
#define BM (BMT * 16)       // 464 nodes per block
#define NBLK 432            // 432 * 464 = 200448 >= 200000; one wave (<=444 resident)
#define SH 84               // A smem row stride in words (336B; ldmatrix conflict-free)
#define IMGW (16 * SH)      // 1344 words per image

#define RBLOCKS 1024
#define RTHREADS 128

// ---------------- device scratch (static: no allocation) ----------------
__device__ float    g_h[2][N_NODES * HSTRIDE];
__device__ float    g_me6T[DEG][N_NODES * 6];    // slice-major: contiguous per j
__device__ int      g_nbrT[DEG][N_NODES];        // slice-major: contiguous per j
__device__ float    g_Wtmp[160 * NB];
__device__ uint32_t g_Bfhi[WARPS * NKT * 2 * 32];   // B fragments (fp16x2), mma order
__device__ uint32_t g_Bflo[WARPS * NKT * 2 * 32];
__device__ float    g_btot[NB];
__device__ float    g_Rc[HDIM * 128];
__device__ float    g_partial[RBLOCKS * 128];

// ---------------- helpers ----------------
__device__ __forceinline__ uint32_t pack_h2(__half a, __half b) {
    __half2 t = __halves2half2(a, b);
    return *(uint32_t*)&t;
}
__device__ __forceinline__ uint32_t h2u(__half2 h) { return *(uint32_t*)&h; }

#define MMA16(C,a0,a1,a2,a3,b0,b1)                                           \
    asm volatile("mma.sync.aligned.m16n8k16.row.col.f32.f16.f16.f32 "        \
        "{%0,%1,%2,%3}, {%4,%5,%6,%7}, {%8,%9}, {%0,%1,%2,%3};"              \
        : "+f"(C[0]), "+f"(C[1]), "+f"(C[2]), "+f"(C[3])                     \
        : "r"(a0), "r"(a1), "r"(a2), "r"(a3), "r"(b0), "r"(b1))

#define LDSM4(R, addr)                                                       \
    asm volatile("ldmatrix.sync.aligned.m8n8.x4.shared.b16 {%0,%1,%2,%3}, [%4];" \
        : "=r"((R)[0]), "=r"((R)[1]), "=r"((R)[2]), "=r"((R)[3]) : "r"(addr))

// ---------------- weight folding -> fp16 mma-fragment images ----------------
// K-slot map: k in [0,70)=U1 ; [72,142)=(Vw@U2) ; [144,150)=U3 ; else 0.
__global__ void prep_kernel(const float* __restrict__ Vw, const float* __restrict__ Vb,
                            const float* __restrict__ Uw, const float* __restrict__ Ub,
                            const float* __restrict__ Rw) {
    int tid = threadIdx.x;
    for (int i = tid; i < 160 * NB; i += blockDim.x) {
        int k = i / NB, n = i % NB;
        float w = 0.f;
        if (n < HDIM) {
            if (k < 70) {
                w = Uw[k * HDIM + n];
            } else if (k >= 72 && k < 142) {
                int p = k - 72;
                float s = 0.f;
                for (int q = 0; q < 70; ++q) s += Vw[p * 70 + q] * Uw[(70 + q) * HDIM + n];
                w = s;
            } else if (k >= 144 && k < 150) {
                w = Uw[(140 + (k - 144)) * HDIM + n];
            }
        }
        g_Wtmp[i] = w;
    }
    __syncthreads();
    // B fragment (m16n8k16): idx = ((w*NKT + kt)*2 + r)*32 + lane
    // packs fp16x2 of W[k0][n], W[k0+1][n], k0 = kt*16 + (lane%4)*2 + 8r, n = w*8 + lane/4
    for (int idx = tid; idx < WARPS * NKT * 2 * 32; idx += blockDim.x) {
        int lane = idx & 31;
        int t = idx >> 5;
        int r = t & 1; t >>= 1;
        int kt = t % NKT;
        int w = t / NKT;
        int k0 = kt * 16 + (lane & 3) * 2 + 8 * r;
        int n = w * 8 + (lane >> 2);
        float v0 = g_Wtmp[k0 * NB + n];
        float v1 = g_Wtmp[(k0 + 1) * NB + n];
        __half h0 = __float2half_rn(v0), h1 = __float2half_rn(v1);
        g_Bfhi[idx] = pack_h2(h0, h1);
        g_Bflo[idx] = pack_h2(__float2half_rn(v0 - __half2float(h0)),
                              __float2half_rn(v1 - __half2float(h1)));
    }
    for (int k = tid; k < NB; k += blockDim.x) {
        float v = 0.f;
        if (k < HDIM) {
            v = Ub[k];
            for (int q = 0; q < 70; ++q) v += Vb[q] * Uw[(70 + q) * HDIM + k];
        }
        g_btot[k] = v;
    }
    for (int i = tid; i < HDIM * 128; i += blockDim.x) {
        int p = i / 128, k = i % 128;
        g_Rc[i] = Rw[p * 128 + k] + Rw[(70 + p) * 128 + k];
    }
}

// ---------------- edge messages -> slice-major; nbr transpose ----------------
__global__ void edge_kernel(const float* __restrict__ ef,
                            const float* __restrict__ Ew,
                            const float* __restrict__ Eb,
                            const int* __restrict__ nbr) {
    int i = blockIdx.x * blockDim.x + threadIdx.x;
    if (i >= N_NODES * DEG) return;
    int node = i / DEG, j = i % DEG;
    float e[6];
#pragma unroll
    for (int d = 0; d < 6; ++d) e[d] = ef[i * 6 + d];
#pragma unroll
    for (int c = 0; c < 6; ++c) {
        float s = __ldg(&Eb[c]);
#pragma unroll
        for (int d = 0; d < 6; ++d) s += e[d] * __ldg(&Ew[d * 6 + c]);
        g_me6T[j][node * 6 + c] = s;
    }
    g_nbrT[j][node] = nbr[i];
}

__global__ void init_kernel(const float* __restrict__ h) {
    int i = blockIdx.x * blockDim.x + threadIdx.x;
    if (i >= N_NODES * HSTRIDE) return;
    int v = i / HSTRIDE, k = i % HSTRIDE;
    g_h[0][i] = (k < HDIM) ? h[v * HDIM + k] : 0.f;
}

// ---------------- split fill: LDG phase (regs) + STS phase (smem) ----------------
// Chunk e of m-tile: r = e/40 (row), q = e%40 (float4 within padded-160 cols).
// cols: self [0,72) | gather [72,144) | me [144,150) | pad [150,160)
__device__ __forceinline__ float4 ldg_chunk(const float* __restrict__ hin,
                                            const int* __restrict__ sg,
                                            const float* __restrict__ mej,
                                            int base, int mt, int r, int q) {
    int node = base + mt * 16 + r;
    if (node > N_NODES - 1) node = N_NODES - 1;
    if (q < 18) {
        return *(const float4*)(hin + (size_t)node * HSTRIDE + 4 * q);
    } else if (q < 36) {
        int gi = sg[mt * 16 + r];
        return *(const float4*)(hin + (size_t)gi * HSTRIDE + 4 * (q - 18));
    } else if (q == 36) {
        const float* me = mej + (size_t)node * 6;
        float2 a = *(const float2*)me;
        float2 b = *(const float2*)(me + 2);
        return make_float4(a.x, a.y, b.x, b.y);
    } else if (q == 37) {
        const float* me = mej + (size_t)node * 6;
        float2 c = *(const float2*)(me + 4);
        return make_float4(c.x, c.y, 0.f, 0.f);
    }
    return make_float4(0.f, 0.f, 0.f, 0.f);   // pad
}

// A smem layout: row-linear fp16 (16 halves per ktile block), hi at [0, IMGW), lo at +IMGW.
__device__ __forceinline__ void sts_chunk(uint32_t* __restrict__ a, int r, int q, float4 v) {
    int base = r * SH + 2 * q;
    __half2 h01 = __float22half2_rn(make_float2(v.x, v.y));
    __half2 h23 = __float22half2_rn(make_float2(v.z, v.w));
    float2 f01 = __half22float2(h01);
    float2 f23 = __half22float2(h23);
    __half2 l01 = __float22half2_rn(make_float2(v.x - f01.x, v.y - f01.y));
    __half2 l23 = __float22half2_rn(make_float2(v.z - f23.x, v.w - f23.y));
    *(uint2*)(a + base)        = make_uint2(h2u(h01), h2u(h23));
    *(uint2*)(a + IMGW + base) = make_uint2(h2u(l01), h2u(l23));
}

// ---------------- one MP step on tensor cores (fp16 3-term split) ----------------
__global__ __launch_bounds__(THREADS, 3)
void step_kernel(int j, int src) {
    __shared__ uint32_t sA[2][2 * IMGW];      // [buffer][hi | lo]
    __shared__ int s_gidx[BM];

    const float* __restrict__ hin = g_h[src];
    float* __restrict__ hout = g_h[src ^ 1];
    const int* __restrict__ nbrj = g_nbrT[j];
    const float* __restrict__ mej = g_me6T[j];
    int tid = threadIdx.x, w = tid >> 5, lane = tid & 31;
    int base = blockIdx.x * BM;

    // B fragments for this warp's 8-column strip: 40 registers (once per block)
    uint32_t Bhi[NKT][2], Blo[NKT][2];
#pragma unroll
    for (int kt = 0; kt < NKT; ++kt)
#pragma unroll
        for (int r = 0; r < 2; ++r) {
            int idx = ((w * NKT + kt) * 2 + r) * 32 + lane;
            Bhi[kt][r] = g_Bfhi[idx];
            Blo[kt][r] = g_Bflo[idx];
        }
    int col = w * 8 + (lane & 3) * 2;
    float bb0 = g_btot[col], bb1 = g_btot[col + 1];

    // gather indices for all 464 nodes of this block
    for (int i = tid; i < BM; i += THREADS) {
        int node = base + i;
        if (node > N_NODES - 1) node = N_NODES - 1;
        s_gidx[i] = __ldg(&nbrj[node]);
    }
    __syncthreads();

    // per-thread chunk ownership: 640 chunks per m-tile; e0 = tid, e1 = tid+288, e2 for tid<64
    const int e0 = tid, e1 = tid + THREADS;
    const int r0 = e0 / 40, q0 = e0 - r0 * 40;
    const int r1 = e1 / 40, q1 = e1 - r1 * 40;
    const bool has2 = (tid < 16 * 40 - 2 * THREADS);   // 64 threads
    const int e2 = tid + 2 * THREADS;
    const int r2 = e2 / 40, q2 = e2 - r2 * 40;

    // prologue: fill tile 0
    {
        float4 v0 = ldg_chunk(hin, s_gidx, mej, base, 0, r0, q0);
        float4 v1 = ldg_chunk(hin, s_gidx, mej, base, 0, r1, q1);
        float4 v2 = has2 ? ldg_chunk(hin, s_gidx, mej, base, 0, r2, q2)
                         : make_float4(0.f, 0.f, 0.f, 0.f);
        sts_chunk(sA[0], r0, q0, v0);
        sts_chunk(sA[0], r1, q1, v1);
        if (has2) sts_chunk(sA[0], r2, q2, v2);
    }
    __syncthreads();

    // ldmatrix lane address
    const int lrow = (lane & 7) + 8 * ((lane >> 3) & 1);
    const int loff = (lrow * SH + ((lane >> 4) & 1) * 4) * 4;   // bytes
    const uint32_t sb0 = (uint32_t)__cvta_generic_to_shared(sA[0]);
    const uint32_t sb1 = (uint32_t)__cvta_generic_to_shared(sA[1]);

#pragma unroll 1
    for (int mt = 0; mt < BMT; ++mt) {
        // (1) issue next tile's global loads into registers
        float4 v0, v1, v2;
        if (mt < BMT - 1) {
            v0 = ldg_chunk(hin, s_gidx, mej, base, mt + 1, r0, q0);
            v1 = ldg_chunk(hin, s_gidx, mej, base, mt + 1, r1, q1);
            if (has2) v2 = ldg_chunk(hin, s_gidx, mej, base, mt + 1, r2, q2);
        }

        // (2) compute current tile
        const uint32_t ahi = ((mt & 1) ? sb1 : sb0) + loff;
        const uint32_t alo = ahi + IMGW * 4;
        float ch[4] = {0.f, 0.f, 0.f, 0.f};
        float cc[4] = {0.f, 0.f, 0.f, 0.f};

#pragma unroll
        for (int kt = 0; kt < NKT; ++kt) {
            uint32_t A[4], L[4];
            LDSM4(A, ahi + kt * 32);
            LDSM4(L, alo + kt * 32);
            MMA16(ch, A[0], A[1], A[2], A[3], Bhi[kt][0], Bhi[kt][1]);
            MMA16(cc, A[0], A[1], A[2], A[3], Blo[kt][0], Blo[kt][1]);
            MMA16(cc, L[0], L[1], L[2], L[3], Bhi[kt][0], Bhi[kt][1]);
        }

        // (3) convert + store next tile into the other buffer
        if (mt < BMT - 1) {
            uint32_t* na = sA[(mt + 1) & 1];
            sts_chunk(na, r0, q0, v0);
            sts_chunk(na, r1, q1, v1);
            if (has2) sts_chunk(na, r2, q2, v2);
        }

        // (4) epilogue: bias + relu, store two float2 per thread
        int row = lane >> 2;
        int node0 = base + mt * 16 + row;
        if (node0 < N_NODES) {
            float2 o;
            o.x = fmaxf((ch[0] + cc[0]) + bb0, 0.f);
            o.y = fmaxf((ch[1] + cc[1]) + bb1, 0.f);
            *(float2*)(hout + (size_t)node0 * HSTRIDE + col) = o;
        }
        int node1 = node0 + 8;
        if (node1 < N_NODES) {
            float2 o;
            o.x = fmaxf((ch[2] + cc[2]) + bb0, 0.f);
            o.y = fmaxf((ch[3] + cc[3]) + bb1, 0.f);
            *(float2*)(hout + (size_t)node1 * HSTRIDE + col) = o;
        }
        __syncthreads();
    }
}

// ---------------- readout ----------------
__global__ __launch_bounds__(RTHREADS)
void readout_kernel(const float* __restrict__ Rb) {
    int k = threadIdx.x;
    float rc[HSTRIDE];
#pragma unroll
    for (int p = 0; p < HDIM; ++p) rc[p] = g_Rc[p * 128 + k];
    rc[70] = 0.f; rc[71] = 0.f;
    float rb = Rb[k];

    int per = (N_NODES + RBLOCKS - 1) / RBLOCKS;
    int n0 = blockIdx.x * per;
    int n1 = n0 + per; if (n1 > N_NODES) n1 = N_NODES;

    float acc = 0.f;
    for (int n = n0; n < n1; ++n) {
        const float4* hp = (const float4*)(g_h[0] + (size_t)n * HSTRIDE);
        float s = rb;
#pragma unroll
        for (int q = 0; q < HSTRIDE / 4; ++q) {
            float4 hv = __ldg(&hp[q]);
            s += hv.x * rc[4 * q] + hv.y * rc[4 * q + 1]
               + hv.z * rc[4 * q + 2] + hv.w * rc[4 * q + 3];
        }
        acc += fmaxf(s, 0.f);
    }
    g_partial[blockIdx.x * 128 + k] = acc;
}

__global__ void final_kernel(const float* __restrict__ S1w, const float* __restrict__ S1b,
                             const float* __restrict__ S2w, const float* __restrict__ S2b,
                             const float* __restrict__ Hw,  const float* __restrict__ Hb,
                             const float* __restrict__ Ow,  const float* __restrict__ Ob,
                             float* __restrict__ out) {
    __shared__ float fm[128], av[128], bv[100], cv[100];
    int t = threadIdx.x;
    float s = 0.f;
    for (int b = 0; b < RBLOCKS; ++b) s += g_partial[b * 128 + t];
    fm[t] = s;
    __syncthreads();
    float v = S1b[t];
    for (int p = 0; p < 128; ++p) v += fm[p] * S1w[p * 128 + t];
    av[t] = fmaxf(v, 0.f);
    __syncthreads();
    if (t < 100) {
        v = S2b[t];
        for (int p = 0; p < 128; ++p) v += av[p] * S2w[p * 100 + t];
        bv[t] = v;
    }
    __syncthreads();
    if (t < 100) {
        v = Hb[t];
        for (int p = 0; p < 100; ++p) v += bv[p] * Hw[p * 100 + t];
        cv[t] = fmaxf(v, 0.f);
    }
    __syncthreads();
    if (t == 0) {
        v = Ob[0];
        for (int p = 0; p < 100; ++p) v += cv[p] * Ow[p];
        out[0] = v;
    }
}

extern "C" void kernel_launch(void* const* d_in, const int* in_sizes, int n_in,
                              void* d_out, int out_size) {
    const float* h   = (const float*)d_in[0];
    const float* ef  = (const float*)d_in[1];
    const int*   nbr = (const int*)d_in[2];
    const float* Vw  = (const float*)d_in[3];
    const float* Vb  = (const float*)d_in[4];
    const float* Ew  = (const float*)d_in[5];
    const float* Eb  = (const float*)d_in[6];
    const float* Uw  = (const float*)d_in[7];
    const float* Ub  = (const float*)d_in[8];
    const float* Rw  = (const float*)d_in[9];
    const float* Rb  = (const float*)d_in[10];
    const float* S1w = (const float*)d_in[11];
    const float* S1b = (const float*)d_in[12];
    const float* S2w = (const float*)d_in[13];
    const float* S2b = (const float*)d_in[14];
    const float* Hw  = (const float*)d_in[15];
    const float* Hb  = (const float*)d_in[16];
    const float* Ow  = (const float*)d_in[17];
    const float* Ob  = (const float*)d_in[18];
    float* out = (float*)d_out;

    prep_kernel<<<1, 256>>>(Vw, Vb, Uw, Ub, Rw);
    edge_kernel<<<(N_NODES * DEG + 255) / 256, 256>>>(ef, Ew, Eb, nbr);
    init_kernel<<<(N_NODES * HSTRIDE + 255) / 256, 256>>>(h);

    int src = 0;
    for (int r = 0; r < T_ROUNDS; ++r) {
        for (int j = 0; j < DEG; ++j) {
            step_kernel<<<NBLK, THREADS>>>(j, src);
            src ^= 1;
        }
    }
    // 48 steps (even) -> final state in g_h[0]
    readout_kernel<<<RBLOCKS, RTHREADS>>>(Rb);
    final_kernel<<<1, 128>>>(S1w, S1b, S2w, S2b, Hw, Hb, Ow, Ob, out);
}

// round 14
// speedup vs baseline: 1.0077x; 1.0064x over previous
#include <cuda_runtime.h>
#include <cuda_fp16.h>
#include <cstdint>

#define N_NODES 200000
#define DEG 16
#define T_ROUNDS 3
#define HDIM 70
#define HSTRIDE 72
#define NKT 10              // K padded to 160 = 10 * 16
#define NB 72
#define WARPS 9
#define THREADS 288
#define BMT 29              // m-tiles (16 nodes) per block
#define BM (BMT * 16)       // 464 nodes per block
#define NBLK 432            // 432 * 464 = 200448 >= 200000; one wave (<=444 resident)
#define SH 84               // A smem row stride in words (336B; ldmatrix conflict-free)
#define IMGW (16 * SH)      // 1344 words per image

#define RBLOCKS 1024
#define RTHREADS 128

// ---------------- device scratch (static: no allocation) ----------------
__device__ float    g_h[2][N_NODES * HSTRIDE];
__device__ float    g_me6T[DEG][N_NODES * 6];    // slice-major: contiguous per j
__device__ int      g_nbrT[DEG][N_NODES];        // slice-major: contiguous per j
__device__ float    g_Wtmp[160 * NB];
__device__ uint32_t g_Bfhi[WARPS * NKT * 2 * 32];   // B fragments (fp16x2), mma order
__device__ uint32_t g_Bflo[WARPS * NKT * 2 * 32];
__device__ float    g_btot[NB];
__device__ float    g_Rc[HDIM * 128];
__device__ float    g_partial[RBLOCKS * 128];

// ---------------- helpers ----------------
__device__ __forceinline__ uint32_t pack_h2(__half a, __half b) {
    __half2 t = __halves2half2(a, b);
    return *(uint32_t*)&t;
}
__device__ __forceinline__ uint32_t h2u(__half2 h) { return *(uint32_t*)&h; }

#define MMA16(C,a0,a1,a2,a3,b0,b1)                                           \
    asm volatile("mma.sync.aligned.m16n8k16.row.col.f32.f16.f16.f32 "        \
        "{%0,%1,%2,%3}, {%4,%5,%6,%7}, {%8,%9}, {%0,%1,%2,%3};"              \
        : "+f"(C[0]), "+f"(C[1]), "+f"(C[2]), "+f"(C[3])                     \
        : "r"(a0), "r"(a1), "r"(a2), "r"(a3), "r"(b0), "r"(b1))

#define LDSM4(R, addr)                                                       \
    asm volatile("ldmatrix.sync.aligned.m8n8.x4.shared.b16 {%0,%1,%2,%3}, [%4];" \
        : "=r"((R)[0]), "=r"((R)[1]), "=r"((R)[2]), "=r"((R)[3]) : "r"(addr))

// ---------------- weight folding -> fp16 mma-fragment images ----------------
// K-slot map: k in [0,70)=U1 ; [72,142)=(Vw@U2) ; [144,150)=U3 ; else 0.
__global__ void prep_kernel(const float* __restrict__ Vw, const float* __restrict__ Vb,
                            const float* __restrict__ Uw, const float* __restrict__ Ub,
                            const float* __restrict__ Rw) {
    int tid = threadIdx.x;
    for (int i = tid; i < 160 * NB; i += blockDim.x) {
        int k = i / NB, n = i % NB;
        float w = 0.f;
        if (n < HDIM) {
            if (k < 70) {
                w = Uw[k * HDIM + n];
            } else if (k >= 72 && k < 142) {
                int p = k - 72;
                float s = 0.f;
                for (int q = 0; q < 70; ++q) s += Vw[p * 70 + q] * Uw[(70 + q) * HDIM + n];
                w = s;
            } else if (k >= 144 && k < 150) {
                w = Uw[(140 + (k - 144)) * HDIM + n];
            }
        }
        g_Wtmp[i] = w;
    }
    __syncthreads();
    // B fragment (m16n8k16): idx = ((w*NKT + kt)*2 + r)*32 + lane
    // packs fp16x2 of W[k0][n], W[k0+1][n], k0 = kt*16 + (lane%4)*2 + 8r, n = w*8 + lane/4
    for (int idx = tid; idx < WARPS * NKT * 2 * 32; idx += blockDim.x) {
        int lane = idx & 31;
        int t = idx >> 5;
        int r = t & 1; t >>= 1;
        int kt = t % NKT;
        int w = t / NKT;
        int k0 = kt * 16 + (lane & 3) * 2 + 8 * r;
        int n = w * 8 + (lane >> 2);
        float v0 = g_Wtmp[k0 * NB + n];
        float v1 = g_Wtmp[(k0 + 1) * NB + n];
        __half h0 = __float2half_rn(v0), h1 = __float2half_rn(v1);
        g_Bfhi[idx] = pack_h2(h0, h1);
        g_Bflo[idx] = pack_h2(__float2half_rn(v0 - __half2float(h0)),
                              __float2half_rn(v1 - __half2float(h1)));
    }
    for (int k = tid; k < NB; k += blockDim.x) {
        float v = 0.f;
        if (k < HDIM) {
            v = Ub[k];
            for (int q = 0; q < 70; ++q) v += Vb[q] * Uw[(70 + q) * HDIM + k];
        }
        g_btot[k] = v;
    }
    for (int i = tid; i < HDIM * 128; i += blockDim.x) {
        int p = i / 128, k = i % 128;
        g_Rc[i] = Rw[p * 128 + k] + Rw[(70 + p) * 128 + k];
    }
}

// ---------------- edge messages -> slice-major; nbr transpose ----------------
__global__ void edge_kernel(const float* __restrict__ ef,
                            const float* __restrict__ Ew,
                            const float* __restrict__ Eb,
                            const int* __restrict__ nbr) {
    int i = blockIdx.x * blockDim.x + threadIdx.x;
    if (i >= N_NODES * DEG) return;
    int node = i / DEG, j = i % DEG;
    float e[6];
#pragma unroll
    for (int d = 0; d < 6; ++d) e[d] = ef[i * 6 + d];
#pragma unroll
    for (int c = 0; c < 6; ++c) {
        float s = __ldg(&Eb[c]);
#pragma unroll
        for (int d = 0; d < 6; ++d) s += e[d] * __ldg(&Ew[d * 6 + c]);
        g_me6T[j][node * 6 + c] = s;
    }
    g_nbrT[j][node] = nbr[i];
}

__global__ void init_kernel(const float* __restrict__ h) {
    int i = blockIdx.x * blockDim.x + threadIdx.x;
    if (i >= N_NODES * HSTRIDE) return;
    int v = i / HSTRIDE, k = i % HSTRIDE;
    g_h[0][i] = (k < HDIM) ? h[v * HDIM + k] : 0.f;
}

// ---------------- split fill: LDG phase (regs) + STS phase (smem) ----------------
// Chunk e of m-tile: r = e/40 (row), q = e%40 (float4 within padded-160 cols).
// cols: self [0,72) | gather [72,144) | me [144,150) | pad [150,160)
__device__ __forceinline__ float4 ldg_chunk(const float* __restrict__ hin,
                                            const int* __restrict__ sg,
                                            const float* __restrict__ mej,
                                            int base, int mt, int r, int q) {
    int node = base + mt * 16 + r;
    if (node > N_NODES - 1) node = N_NODES - 1;
    if (q < 18) {
        return *(const float4*)(hin + (size_t)node * HSTRIDE + 4 * q);
    } else if (q < 36) {
        int gi = sg[mt * 16 + r];
        return *(const float4*)(hin + (size_t)gi * HSTRIDE + 4 * (q - 18));
    } else if (q == 36) {
        const float* me = mej + (size_t)node * 6;
        float2 a = *(const float2*)me;
        float2 b = *(const float2*)(me + 2);
        return make_float4(a.x, a.y, b.x, b.y);
    } else if (q == 37) {
        const float* me = mej + (size_t)node * 6;
        float2 c = *(const float2*)(me + 4);
        return make_float4(c.x, c.y, 0.f, 0.f);
    }
    return make_float4(0.f, 0.f, 0.f, 0.f);   // pad
}

// A smem layout: row-linear fp16 (16 halves per ktile block), hi at [0, IMGW), lo at +IMGW.
__device__ __forceinline__ void sts_chunk(uint32_t* __restrict__ a, int r, int q, float4 v) {
    int base = r * SH + 2 * q;
    __half2 h01 = __float22half2_rn(make_float2(v.x, v.y));
    __half2 h23 = __float22half2_rn(make_float2(v.z, v.w));
    float2 f01 = __half22float2(h01);
    float2 f23 = __half22float2(h23);
    __half2 l01 = __float22half2_rn(make_float2(v.x - f01.x, v.y - f01.y));
    __half2 l23 = __float22half2_rn(make_float2(v.z - f23.x, v.w - f23.y));
    *(uint2*)(a + base)        = make_uint2(h2u(h01), h2u(h23));
    *(uint2*)(a + IMGW + base) = make_uint2(h2u(l01), h2u(l23));
}

// ---------------- one MP step on tensor cores (fp16 3-term split) ----------------
__global__ __launch_bounds__(THREADS, 3)
void step_kernel(int j, int src) {
    __shared__ uint32_t sA[2][2 * IMGW];      // [buffer][hi | lo]
    __shared__ int s_gidx[BM];

    const float* __restrict__ hin = g_h[src];
    float* __restrict__ hout = g_h[src ^ 1];
    const int* __restrict__ nbrj = g_nbrT[j];
    const float* __restrict__ mej = g_me6T[j];
    int tid = threadIdx.x, w = tid >> 5, lane = tid & 31;
    int base = blockIdx.x * BM;

    // B fragments for this warp's 8-column strip: 40 registers (once per block)
    uint32_t Bhi[NKT][2], Blo[NKT][2];
#pragma unroll
    for (int kt = 0; kt < NKT; ++kt)
#pragma unroll
        for (int r = 0; r < 2; ++r) {
            int idx = ((w * NKT + kt) * 2 + r) * 32 + lane;
            Bhi[kt][r] = g_Bfhi[idx];
            Blo[kt][r] = g_Bflo[idx];
        }
    int col = w * 8 + (lane & 3) * 2;
    float bb0 = g_btot[col], bb1 = g_btot[col + 1];

    // gather indices for all 464 nodes of this block
    for (int i = tid; i < BM; i += THREADS) {
        int node = base + i;
        if (node > N_NODES - 1) node = N_NODES - 1;
        s_gidx[i] = __ldg(&nbrj[node]);
    }
    __syncthreads();

    // per-thread chunk ownership: 640 chunks per m-tile; e0 = tid, e1 = tid+288, e2 for tid<64
    const int e0 = tid, e1 = tid + THREADS;
    const int r0 = e0 / 40, q0 = e0 - r0 * 40;
    const int r1 = e1 / 40, q1 = e1 - r1 * 40;
    const bool has2 = (tid < 16 * 40 - 2 * THREADS);   // 64 threads
    const int e2 = tid + 2 * THREADS;
    const int r2 = e2 / 40, q2 = e2 - r2 * 40;

    // prologue: fill tile 0
    {
        float4 v0 = ldg_chunk(hin, s_gidx, mej, base, 0, r0, q0);
        float4 v1 = ldg_chunk(hin, s_gidx, mej, base, 0, r1, q1);
        float4 v2 = has2 ? ldg_chunk(hin, s_gidx, mej, base, 0, r2, q2)
                         : make_float4(0.f, 0.f, 0.f, 0.f);
        sts_chunk(sA[0], r0, q0, v0);
        sts_chunk(sA[0], r1, q1, v1);
        if (has2) sts_chunk(sA[0], r2, q2, v2);
    }
    __syncthreads();

    // ldmatrix lane address
    const int lrow = (lane & 7) + 8 * ((lane >> 3) & 1);
    const int loff = (lrow * SH + ((lane >> 4) & 1) * 4) * 4;   // bytes
    const uint32_t sb0 = (uint32_t)__cvta_generic_to_shared(sA[0]);
    const uint32_t sb1 = (uint32_t)__cvta_generic_to_shared(sA[1]);

#pragma unroll 1
    for (int mt = 0; mt < BMT; ++mt) {
        // (1) issue next tile's global loads into registers
        float4 v0, v1, v2;
        if (mt < BMT - 1) {
            v0 = ldg_chunk(hin, s_gidx, mej, base, mt + 1, r0, q0);
            v1 = ldg_chunk(hin, s_gidx, mej, base, mt + 1, r1, q1);
            if (has2) v2 = ldg_chunk(hin, s_gidx, mej, base, mt + 1, r2, q2);
        }

        // (2) compute current tile
        const uint32_t ahi = ((mt & 1) ? sb1 : sb0) + loff;
        const uint32_t alo = ahi + IMGW * 4;
        float ch[4] = {0.f, 0.f, 0.f, 0.f};
        float cc[4] = {0.f, 0.f, 0.f, 0.f};

#pragma unroll
        for (int kt = 0; kt < NKT; ++kt) {
            uint32_t A[4], L[4];
            LDSM4(A, ahi + kt * 32);
            LDSM4(L, alo + kt * 32);
            MMA16(ch, A[0], A[1], A[2], A[3], Bhi[kt][0], Bhi[kt][1]);
            MMA16(cc, A[0], A[1], A[2], A[3], Blo[kt][0], Blo[kt][1]);
            MMA16(cc, L[0], L[1], L[2], L[3], Bhi[kt][0], Bhi[kt][1]);
        }

        // (3) convert + store next tile into the other buffer
        if (mt < BMT - 1) {
            uint32_t* na = sA[(mt + 1) & 1];
            sts_chunk(na, r0, q0, v0);
            sts_chunk(na, r1, q1, v1);
            if (has2) sts_chunk(na, r2, q2, v2);
        }

        // (4) epilogue: bias + relu, store two float2 per thread
        int row = lane >> 2;
        int node0 = base + mt * 16 + row;
        if (node0 < N_NODES) {
            float2 o;
            o.x = fmaxf((ch[0] + cc[0]) + bb0, 0.f);
            o.y = fmaxf((ch[1] + cc[1]) + bb1, 0.f);
            *(float2*)(hout + (size_t)node0 * HSTRIDE + col) = o;
        }
        int node1 = node0 + 8;
        if (node1 < N_NODES) {
            float2 o;
            o.x = fmaxf((ch[2] + cc[2]) + bb0, 0.f);
            o.y = fmaxf((ch[3] + cc[3]) + bb1, 0.f);
            *(float2*)(hout + (size_t)node1 * HSTRIDE + col) = o;
        }
        __syncthreads();
    }
}

// ---------------- readout ----------------
__global__ __launch_bounds__(RTHREADS)
void readout_kernel(const float* __restrict__ Rb) {
    int k = threadIdx.x;
    float rc[HSTRIDE];
#pragma unroll
    for (int p = 0; p < HDIM; ++p) rc[p] = g_Rc[p * 128 + k];
    rc[70] = 0.f; rc[71] = 0.f;
    float rb = Rb[k];

    int per = (N_NODES + RBLOCKS - 1) / RBLOCKS;
    int n0 = blockIdx.x * per;
    int n1 = n0 + per; if (n1 > N_NODES) n1 = N_NODES;

    float acc = 0.f;
    for (int n = n0; n < n1; ++n) {
        const float4* hp = (const float4*)(g_h[0] + (size_t)n * HSTRIDE);
        float s = rb;
#pragma unroll
        for (int q = 0; q < HSTRIDE / 4; ++q) {
            float4 hv = __ldg(&hp[q]);
            s += hv.x * rc[4 * q] + hv.y * rc[4 * q + 1]
               + hv.z * rc[4 * q + 2] + hv.w * rc[4 * q + 3];
        }
        acc += fmaxf(s, 0.f);
    }
    g_partial[blockIdx.x * 128 + k] = acc;
}

__global__ void final_kernel(const float* __restrict__ S1w, const float* __restrict__ S1b,
                             const float* __restrict__ S2w, const float* __restrict__ S2b,
                             const float* __restrict__ Hw,  const float* __restrict__ Hb,
                             const float* __restrict__ Ow,  const float* __restrict__ Ob,
                             float* __restrict__ out) {
    __shared__ float fm[128], av[128], bv[100], cv[100];
    int t = threadIdx.x;
    float s = 0.f;
    for (int b = 0; b < RBLOCKS; ++b) s += g_partial[b * 128 + t];
    fm[t] = s;
    __syncthreads();
    float v = S1b[t];
    for (int p = 0; p < 128; ++p) v += fm[p] * S1w[p * 128 + t];
    av[t] = fmaxf(v, 0.f);
    __syncthreads();
    if (t < 100) {
        v = S2b[t];
        for (int p = 0; p < 128; ++p) v += av[p] * S2w[p * 100 + t];
        bv[t] = v;
    }
    __syncthreads();
    if (t < 100) {
        v = Hb[t];
        for (int p = 0; p < 100; ++p) v += bv[p] * Hw[p * 100 + t];
        cv[t] = fmaxf(v, 0.f);
    }
    __syncthreads();
    if (t == 0) {
        v = Ob[0];
        for (int p = 0; p < 100; ++p) v += cv[p] * Ow[p];
        out[0] = v;
    }
}

extern "C" void kernel_launch(void* const* d_in, const int* in_sizes, int n_in,
                              void* d_out, int out_size) {
    const float* h   = (const float*)d_in[0];
    const float* ef  = (const float*)d_in[1];
    const int*   nbr = (const int*)d_in[2];
    const float* Vw  = (const float*)d_in[3];
    const float* Vb  = (const float*)d_in[4];
    const float* Ew  = (const float*)d_in[5];
    const float* Eb  = (const float*)d_in[6];
    const float* Uw  = (const float*)d_in[7];
    const float* Ub  = (const float*)d_in[8];
    const float* Rw  = (const float*)d_in[9];
    const float* Rb  = (const float*)d_in[10];
    const float* S1w = (const float*)d_in[11];
    const float* S1b = (const float*)d_in[12];
    const float* S2w = (const float*)d_in[13];
    const float* S2b = (const float*)d_in[14];
    const float* Hw  = (const float*)d_in[15];
    const float* Hb  = (const float*)d_in[16];
    const float* Ow  = (const float*)d_in[17];
    const float* Ob  = (const float*)d_in[18];
    float* out = (float*)d_out;

    prep_kernel<<<1, 256>>>(Vw, Vb, Uw, Ub, Rw);
    edge_kernel<<<(N_NODES * DEG + 255) / 256, 256>>>(ef, Ew, Eb, nbr);
    init_kernel<<<(N_NODES * HSTRIDE + 255) / 256, 256>>>(h);

    int src = 0;
    for (int r = 0; r < T_ROUNDS; ++r) {
        for (int j = 0; j < DEG; ++j) {
            step_kernel<<<NBLK, THREADS>>>(j, src);
            src ^= 1;
        }
    }
    // 48 steps (even) -> final state in g_h[0]
    readout_kernel<<<RBLOCKS, RTHREADS>>>(Rb);
    final_kernel<<<1, 128>>>(S1w, S1b, S2w, S2b, Hw, Hb, Ow, Ob, out);
}